// round 11
// baseline (speedup 1.0000x reference)
#include <cuda_runtime.h>
#include <cuda_fp16.h>
#include <cstdint>

// LinearEmbedded via single-pass fp16 mma.sync (fp32 accumulate).
// out[a,b,d] = sum_c x[a,b,c]*W[r_b,c,d] + bias[r_b,d]; A=B=128, C=D=512.
// R10: R7 skeleton (2 CTAs/SM, immediate cvt, 1 barrier/chunk) with K-chunk
// doubled to 64 -> 8 barriers/CTA instead of 16, 2x compute per latency
// window. CTA tile 128(a) x 64(d) (fits 128-reg cap for 2 CTAs/SM),
// grid (8,128) = 1024 CTAs. 2 stages x 24KB = 48KB static smem.
// 8 warps as 4(m)x2(n) -> warp tile 32x32: 16 ldsm + 32 MMA per chunk.
// SMEM tiles in ldmatrix lane order (16B chunk index == lane) -> LDSM and
// producer st.128 both conflict-free.

__device__ int g_ridx[128];

__global__ void decode_idx_kernel(const unsigned int* __restrict__ p, int n) {
    __shared__ int not_i64;
    if (threadIdx.x == 0) not_i64 = 0;
    __syncthreads();
    if (threadIdx.x < 64) {
        if (p[2 * threadIdx.x + 1] != 0u) not_i64 = 1;
    }
    __syncthreads();
    int b = (int)threadIdx.x;
    if (b < n) g_ridx[b] = not_i64 ? (int)p[b] : (int)p[2 * b];
}

__device__ __forceinline__ uint32_t smem_u32(const void* p) {
    uint32_t a;
    asm("{ .reg .u64 t; cvta.to.shared.u64 t, %1; cvt.u32.u64 %0, t; }" : "=r"(a) : "l"(p));
    return a;
}

__device__ __forceinline__ uint32_t cvt2(float v0, float v1) {
    __half2 h = __floats2half2_rn(v0, v1);
    return *(uint32_t*)&h;
}

__device__ __forceinline__ void ldsm4(uint32_t* r, uint32_t addr) {
    asm volatile("ldmatrix.sync.aligned.m8n8.x4.shared.b16 {%0,%1,%2,%3}, [%4];"
        : "=r"(r[0]), "=r"(r[1]), "=r"(r[2]), "=r"(r[3]) : "r"(addr));
}

__device__ __forceinline__ void mma16816(float* d, const uint32_t* a, uint32_t b0, uint32_t b1) {
    asm volatile("mma.sync.aligned.m16n8k16.row.col.f32.f16.f16.f32 "
        "{%0,%1,%2,%3}, {%4,%5,%6,%7}, {%8,%9}, {%0,%1,%2,%3};"
        : "+f"(d[0]), "+f"(d[1]), "+f"(d[2]), "+f"(d[3])
        : "r"(a[0]), "r"(a[1]), "r"(a[2]), "r"(a[3]), "r"(b0), "r"(b1));
}

// Per-stage (24 KB):
//   A (x, 128a x 64k fp16): [k16:4][t16:8] tiles x 512B = 16KB at 0
//   B (W,  64d x 64k fp16): [k16:4][t16:4] tiles x 512B =  8KB at 16384
#define A_OFF 0
#define B_OFF 16384
#define STAGE_BYTES 24576

__global__ __launch_bounds__(256, 2)
void linemb_mma(const float* __restrict__ x,
                const float* __restrict__ w,
                const float* __restrict__ bias,
                float* __restrict__ out) {
    __shared__ __align__(16) char smem[2 * STAGE_BYTES];   // 48KB static
    const uint32_t sb = smem_u32(smem);

    const int tid  = (int)threadIdx.x;
    const int wid  = tid >> 5;
    const int lane = tid & 31;
    const int b    = (int)blockIdx.y;
    const int d0   = (int)blockIdx.x * 64;
    const int r    = g_ridx[b];

    const float* __restrict__ xb = x + (size_t)b * 512;          // + a*65536 + c
    const float* __restrict__ wr = w + (size_t)r * 512 * 512;    // + c*512 + d
    const float* __restrict__ br = bias + (size_t)r * 512;

    // ---- W producer: thread -> (d = tid&63, 2 k-octets o = (tid>>6)*2 + j)
    const int w_d   = tid & 63;
    const int w_o0  = (tid >> 6) * 2;    // 0,2,4,6
    uint32_t boff[2];
    {
        const int n = w_d & 15, t16 = w_d >> 4;
        #pragma unroll
        for (int j = 0; j < 2; ++j) {
            const int o = w_o0 + j, k16 = o >> 1, oc = o & 1;
            boff[j] = (uint32_t)((k16 * 4 + t16) * 512 + ((n & 7) + 8 * (oc + 2 * (n >> 3))) * 16);
        }
    }
    // ---- x producer: thread -> (a = tid&127, 4 k-octets o = (tid>>7)*4 + j)
    const int x_a  = tid & 127;
    const int x_o0 = (tid >> 7) * 4;     // 0 or 4
    uint32_t aoff[4];
    {
        const int n = x_a & 15, t16 = x_a >> 4;
        #pragma unroll
        for (int j = 0; j < 4; ++j) {
            const int o = x_o0 + j, k16 = o >> 1, oc = o & 1;
            aoff[j] = (uint32_t)((k16 * 8 + t16) * 512 + ((n & 7) + 8 * ((n >> 3) & 1) + 16 * oc) * 16);
        }
    }

    const float* wbase = wr + (size_t)w_o0 * 8 * 512 + d0 + w_d;  // + k*512
    const float* xbase = xb + (size_t)x_a * 65536 + x_o0 * 8;     // + k

    uint32_t wh[8], xh[16];   // converted fp16x2 prefetch

    // ---- prefetch + convert chunk 0 ----
    #pragma unroll
    for (int j = 0; j < 2; ++j) {
        float v[8];
        #pragma unroll
        for (int i = 0; i < 8; ++i)
            v[i] = __ldg(wbase + (size_t)(j * 8 + i) * 512);
        #pragma unroll
        for (int p = 0; p < 4; ++p)
            wh[j * 4 + p] = cvt2(v[2 * p], v[2 * p + 1]);
    }
    #pragma unroll
    for (int j = 0; j < 4; ++j) {
        const float4 p0 = *(const float4*)(xbase + j * 8);
        const float4 p1 = *(const float4*)(xbase + j * 8 + 4);
        xh[j * 4 + 0] = cvt2(p0.x, p0.y);
        xh[j * 4 + 1] = cvt2(p0.z, p0.w);
        xh[j * 4 + 2] = cvt2(p1.x, p1.y);
        xh[j * 4 + 3] = cvt2(p1.z, p1.w);
    }

    float acc[2][4][4];
    #pragma unroll
    for (int mt = 0; mt < 2; ++mt)
        #pragma unroll
        for (int nb = 0; nb < 4; ++nb)
            #pragma unroll
            for (int q = 0; q < 4; ++q)
                acc[mt][nb][q] = 0.0f;

    const int wm = wid & 3;   // 4 m-groups of 32 (a)
    const int wn = wid >> 2;  // 2 n-groups of 32 (d)

    for (int ch = 0; ch < 8; ++ch) {        // 8 chunks of K=64
        const uint32_t st = sb + (uint32_t)((ch & 1) * STAGE_BYTES);

        // ---- store prefetched chunk into stage ----
        #pragma unroll
        for (int j = 0; j < 2; ++j)
            asm volatile("st.shared.v4.b32 [%0], {%1,%2,%3,%4};"
                :: "r"(st + B_OFF + boff[j]), "r"(wh[j*4+0]), "r"(wh[j*4+1]), "r"(wh[j*4+2]), "r"(wh[j*4+3]) : "memory");
        #pragma unroll
        for (int j = 0; j < 4; ++j)
            asm volatile("st.shared.v4.b32 [%0], {%1,%2,%3,%4};"
                :: "r"(st + A_OFF + aoff[j]), "r"(xh[j*4+0]), "r"(xh[j*4+1]), "r"(xh[j*4+2]), "r"(xh[j*4+3]) : "memory");

        // ---- prefetch + convert next chunk ----
        if (ch + 1 < 8) {
            const int k0 = (ch + 1) * 64;
            #pragma unroll
            for (int j = 0; j < 2; ++j) {
                float v[8];
                #pragma unroll
                for (int i = 0; i < 8; ++i)
                    v[i] = __ldg(wbase + (size_t)(k0 + j * 8 + i) * 512);
                #pragma unroll
                for (int p = 0; p < 4; ++p)
                    wh[j * 4 + p] = cvt2(v[2 * p], v[2 * p + 1]);
            }
            #pragma unroll
            for (int j = 0; j < 4; ++j) {
                const float4 p0 = *(const float4*)(xbase + k0 + j * 8);
                const float4 p1 = *(const float4*)(xbase + k0 + j * 8 + 4);
                xh[j * 4 + 0] = cvt2(p0.x, p0.y);
                xh[j * 4 + 1] = cvt2(p0.z, p0.w);
                xh[j * 4 + 2] = cvt2(p1.x, p1.y);
                xh[j * 4 + 3] = cvt2(p1.z, p1.w);
            }
        }

        // Single barrier per chunk: with 2 stages, barrier(ch-1) already
        // ordered compute(ch-2) on this stage before our stores above.
        __syncthreads();

        // ---- compute: 4 k16-steps ----
        #pragma unroll
        for (int k16 = 0; k16 < 4; ++k16) {
            uint32_t ah[2][4], bh[2][4];
            const uint32_t lof = (uint32_t)lane * 16;
            #pragma unroll
            for (int mt = 0; mt < 2; ++mt)
                ldsm4(ah[mt], st + A_OFF + (uint32_t)((k16 * 8 + wm * 2 + mt) * 512) + lof);
            #pragma unroll
            for (int nt = 0; nt < 2; ++nt)
                ldsm4(bh[nt], st + B_OFF + (uint32_t)((k16 * 4 + wn * 2 + nt) * 512) + lof);
            #pragma unroll
            for (int mt = 0; mt < 2; ++mt) {
                #pragma unroll
                for (int nb = 0; nb < 4; ++nb) {
                    const int nt = nb >> 1, hh = (nb & 1) * 2;
                    mma16816(acc[mt][nb], ah[mt], bh[nt][hh], bh[nt][hh + 1]);
                }
            }
        }
    }

    // ---- epilogue: add bias, store out[a][b][d] ----
    const int tq = lane & 3;    // -> d pair
    const int tg = lane >> 2;   // -> row within 8
    #pragma unroll
    for (int nb = 0; nb < 4; ++nb) {
        const int d = d0 + wn * 32 + nb * 8 + 2 * tq;
        const float2 bv = *(const float2*)(br + d);
        #pragma unroll
        for (int mt = 0; mt < 2; ++mt) {
            const int a0r = wm * 32 + mt * 16 + tg;
            float2 o0, o1;
            o0.x = acc[mt][nb][0] + bv.x;
            o0.y = acc[mt][nb][1] + bv.y;
            o1.x = acc[mt][nb][2] + bv.x;
            o1.y = acc[mt][nb][3] + bv.y;
            *(float2*)(out + ((size_t)a0r * 128 + b) * 512 + d)       = o0;
            *(float2*)(out + ((size_t)(a0r + 8) * 128 + b) * 512 + d) = o1;
        }
    }
}

extern "C" void kernel_launch(void* const* d_in, const int* in_sizes, int n_in,
                              void* d_out, int out_size) {
    const float*        x    = (const float*)d_in[0];
    const unsigned int* ridx = (const unsigned int*)d_in[1];
    const float*        w    = (const float*)d_in[2];
    const float*        bias = (const float*)d_in[3];
    float*              out  = (float*)d_out;

    const int Bn = in_sizes[1] > 128 ? 128 : in_sizes[1];
    decode_idx_kernel<<<1, 128>>>(ridx, Bn);

    dim3 grid(8, 128);   // (d-tiles, b)
    linemb_mma<<<grid, 256>>>(x, w, bias, out);
}

// round 12
// speedup vs baseline: 1.3140x; 1.3140x over previous
#include <cuda_runtime.h>
#include <cuda_fp16.h>
#include <cstdint>

// LinearEmbedded via fp16 mma.sync + cp.async 4-stage fp32 staging.
// out[a,b,d] = sum_c x[a,b,c]*W[r_b,c,d] + bias[r_b,d]; A=B=128, C=D=512.
// R11: producer = cp.async.cg (no register dependency -> 4 chunks in flight,
// DRAM-saturating MLP). Consumer per chunk: LDS fp32 -> cvt -> STS fp16
// (ldsm lane-order) -> ldsm -> mma; all short-latency smem ops.
// CTA tile 128x128, 256 thr, warp 2(m)x4(n) (64x32), K-chunk 32.
// SMEM: 4 fp32 x-stages (160B-padded rows) + 4 fp32 W-stages + 2 fp16 stages
// = 176KB dynamic, 1 CTA/SM, grid (4,128)=512 CTAs.

__device__ int g_ridx[128];

__global__ void decode_idx_kernel(const unsigned int* __restrict__ p, int n) {
    __shared__ int not_i64;
    if (threadIdx.x == 0) not_i64 = 0;
    __syncthreads();
    if (threadIdx.x < 64) {
        if (p[2 * threadIdx.x + 1] != 0u) not_i64 = 1;
    }
    __syncthreads();
    int b = (int)threadIdx.x;
    if (b < n) g_ridx[b] = not_i64 ? (int)p[b] : (int)p[2 * b];
}

__device__ __forceinline__ uint32_t smem_u32(const void* p) {
    uint32_t a;
    asm("{ .reg .u64 t; cvta.to.shared.u64 t, %1; cvt.u32.u64 %0, t; }" : "=r"(a) : "l"(p));
    return a;
}

__device__ __forceinline__ uint32_t cvt2(float v0, float v1) {
    __half2 h = __floats2half2_rn(v0, v1);
    return *(uint32_t*)&h;
}

__device__ __forceinline__ void cp16(uint32_t dst, const void* src) {
    asm volatile("cp.async.cg.shared.global [%0], [%1], 16;" :: "r"(dst), "l"(src) : "memory");
}

__device__ __forceinline__ void ldsm4(uint32_t* r, uint32_t addr) {
    asm volatile("ldmatrix.sync.aligned.m8n8.x4.shared.b16 {%0,%1,%2,%3}, [%4];"
        : "=r"(r[0]), "=r"(r[1]), "=r"(r[2]), "=r"(r[3]) : "r"(addr));
}

__device__ __forceinline__ void mma16816(float* d, const uint32_t* a, uint32_t b0, uint32_t b1) {
    asm volatile("mma.sync.aligned.m16n8k16.row.col.f32.f16.f16.f32 "
        "{%0,%1,%2,%3}, {%4,%5,%6,%7}, {%8,%9}, {%0,%1,%2,%3};"
        : "+f"(d[0]), "+f"(d[1]), "+f"(d[2]), "+f"(d[3])
        : "r"(a[0]), "r"(a[1]), "r"(a[2]), "r"(a[3]), "r"(b0), "r"(b1));
}

// SMEM map (dynamic, 176KB):
//  XF: 4 stages x (128 rows x 160B) = 81920   at 0       (fp32 x, padded rows)
//  WF: 4 stages x (32 rows  x 512B) = 65536   at 81920   (fp32 W, [k][d])
//  H : 2 stages x 16KB              = 32768   at 147456  (fp16 ldsm tiles)
#define XF_OFF 0
#define XF_STAGE 20480
#define WF_OFF 81920
#define WF_STAGE 16384
#define H_OFF 147456
#define H_STAGE 16384
#define HA_OFF 0          // within H stage: A (x) 8KB
#define HB_OFF 8192       //                 B (W) 8KB
#define SMEM_TOTAL 180224

__global__ __launch_bounds__(256, 1)
void linemb_mma(const float* __restrict__ x,
                const float* __restrict__ w,
                const float* __restrict__ bias,
                float* __restrict__ out) {
    extern __shared__ __align__(16) char smem[];
    const uint32_t sb = smem_u32(smem);

    const int tid  = (int)threadIdx.x;
    const int wid  = tid >> 5;
    const int lane = tid & 31;
    const int b    = (int)blockIdx.y;
    const int d0   = (int)blockIdx.x * 128;
    const int r    = g_ridx[b];

    const float* __restrict__ xb = x + (size_t)b * 512;          // + a*65536 + c
    const float* __restrict__ wr = w + (size_t)r * 512 * 512;    // + c*512 + d
    const float* __restrict__ br = bias + (size_t)r * 512;

    // ---- cp.async producer mappings ----
    // W: granule g = tid + 256*j (j=0..3): k = g>>5, seg = g&31 (16B segs of a
    //    512B row) -> warp covers one full row: perfectly coalesced.
    // x: thread -> (row = tid>>1, segs (tid&1)*4 + 0..3): 64B contiguous per
    //    thread of the row's 128B chunk slab.
    const int x_row  = tid >> 1;
    const int x_seg0 = (tid & 1) * 4;
    const float* xsrc = xb + (size_t)x_row * 65536 + x_seg0 * 4;   // + k0
    const uint32_t xdst = sb + XF_OFF + (uint32_t)(x_row * 160 + x_seg0 * 16);

    // ---- converter mappings (R7 fp16 lane-order tiles) ----
    const int c_row = tid & 127;          // x: a row / W: d row
    const int c_o0  = (tid >> 7) * 2;     // first k-octet (0 or 2)
    uint32_t aoff[2], boff[2];
    {
        const int n = c_row & 15, t16 = c_row >> 4;
        #pragma unroll
        for (int j = 0; j < 2; ++j) {
            const int o = c_o0 + j, k16 = o >> 1, oc = o & 1;
            aoff[j] = (uint32_t)((k16 * 8 + t16) * 512 + ((n & 7) + 8 * ((n >> 3) & 1) + 16 * oc) * 16);
            boff[j] = (uint32_t)((k16 * 8 + t16) * 512 + ((n & 7) + 8 * (oc + 2 * (n >> 3))) * 16);
        }
    }

    // ---- prologue: issue stages 0..3 ----
    #pragma unroll
    for (int s = 0; s < 4; ++s) {
        const int k0 = s * 32;
        const uint32_t xfs = sb + XF_OFF + (uint32_t)(s * XF_STAGE);
        const uint32_t wfs = sb + WF_OFF + (uint32_t)(s * WF_STAGE);
        #pragma unroll
        for (int j = 0; j < 4; ++j) {
            const int g = tid + 256 * j;
            const int k = g >> 5, seg = g & 31;
            cp16(wfs + (uint32_t)(k * 512 + seg * 16),
                 wr + (size_t)(k0 + k) * 512 + d0 + seg * 4);
        }
        #pragma unroll
        for (int j = 0; j < 4; ++j)
            cp16(xdst - (sb + XF_OFF) + xfs + (uint32_t)(j * 16), xsrc + k0 + j * 4);
        asm volatile("cp.async.commit_group;" ::: "memory");
    }

    float acc[4][4][4];
    #pragma unroll
    for (int mt = 0; mt < 4; ++mt)
        #pragma unroll
        for (int nb = 0; nb < 4; ++nb)
            #pragma unroll
            for (int q = 0; q < 4; ++q)
                acc[mt][nb][q] = 0.0f;

    const int wm = wid & 1;   // 2 m-groups of 64 (a)
    const int wn = wid >> 1;  // 4 n-groups of 32 (d)

    for (int ch = 0; ch < 16; ++ch) {
        const uint32_t xfs = sb + XF_OFF + (uint32_t)((ch & 3) * XF_STAGE);
        const uint32_t wfs = sb + WF_OFF + (uint32_t)((ch & 3) * WF_STAGE);
        const uint32_t hs  = sb + H_OFF  + (uint32_t)((ch & 1) * H_STAGE);

        // 1) stage ch's cp.async groups done (<=3 younger pending)
        asm volatile("cp.async.wait_group 3;" ::: "memory");
        __syncthreads();   // make all threads' arrivals visible

        // 2) convert fp32 stage -> fp16 ldsm tiles
        #pragma unroll
        for (int j = 0; j < 2; ++j) {
            const int o = c_o0 + j;
            // x: 8 consecutive fp32 from row c_row
            float4 q0, q1;
            asm volatile("ld.shared.v4.f32 {%0,%1,%2,%3}, [%4];"
                : "=f"(q0.x), "=f"(q0.y), "=f"(q0.z), "=f"(q0.w)
                : "r"(xfs + (uint32_t)(c_row * 160 + o * 32)));
            asm volatile("ld.shared.v4.f32 {%0,%1,%2,%3}, [%4];"
                : "=f"(q1.x), "=f"(q1.y), "=f"(q1.z), "=f"(q1.w)
                : "r"(xfs + (uint32_t)(c_row * 160 + o * 32 + 16)));
            uint32_t h0 = cvt2(q0.x, q0.y), h1 = cvt2(q0.z, q0.w);
            uint32_t h2 = cvt2(q1.x, q1.y), h3 = cvt2(q1.z, q1.w);
            asm volatile("st.shared.v4.b32 [%0], {%1,%2,%3,%4};"
                :: "r"(hs + HA_OFF + aoff[j]), "r"(h0), "r"(h1), "r"(h2), "r"(h3) : "memory");
            // W: 8 k-values at fixed d (column read, conflict-free)
            float v[8];
            #pragma unroll
            for (int i = 0; i < 8; ++i)
                asm volatile("ld.shared.f32 %0, [%1];"
                    : "=f"(v[i]) : "r"(wfs + (uint32_t)((o * 8 + i) * 512 + c_row * 4)));
            h0 = cvt2(v[0], v[1]); h1 = cvt2(v[2], v[3]);
            h2 = cvt2(v[4], v[5]); h3 = cvt2(v[6], v[7]);
            asm volatile("st.shared.v4.b32 [%0], {%1,%2,%3,%4};"
                :: "r"(hs + HB_OFF + boff[j]), "r"(h0), "r"(h1), "r"(h2), "r"(h3) : "memory");
        }

        // 3) converts done; fp32 slot ch&3 free; fp16 slot ch&1 full
        __syncthreads();

        // 4) refill fp32 slot with chunk ch+4 (or empty commit to keep FIFO)
        if (ch + 4 < 16) {
            const int k0 = (ch + 4) * 32;
            #pragma unroll
            for (int j = 0; j < 4; ++j) {
                const int g = tid + 256 * j;
                const int k = g >> 5, seg = g & 31;
                cp16(wfs + (uint32_t)(k * 512 + seg * 16),
                     wr + (size_t)(k0 + k) * 512 + d0 + seg * 4);
            }
            #pragma unroll
            for (int j = 0; j < 4; ++j)
                cp16(xfs + (uint32_t)(x_row * 160 + (x_seg0 + j) * 16), xsrc + k0 + j * 4);
        }
        asm volatile("cp.async.commit_group;" ::: "memory");

        // 5) compute: 2 k16-steps from fp16 stage
        #pragma unroll
        for (int k16 = 0; k16 < 2; ++k16) {
            uint32_t ah[4][4], bh[2][4];
            const uint32_t lof = (uint32_t)lane * 16;
            #pragma unroll
            for (int mt = 0; mt < 4; ++mt)
                ldsm4(ah[mt], hs + HA_OFF + (uint32_t)((k16 * 8 + wm * 4 + mt) * 512) + lof);
            #pragma unroll
            for (int nt = 0; nt < 2; ++nt)
                ldsm4(bh[nt], hs + HB_OFF + (uint32_t)((k16 * 8 + wn * 2 + nt) * 512) + lof);
            #pragma unroll
            for (int mt = 0; mt < 4; ++mt) {
                #pragma unroll
                for (int nb = 0; nb < 4; ++nb) {
                    const int nt = nb >> 1, hh = (nb & 1) * 2;
                    mma16816(acc[mt][nb], ah[mt], bh[nt][hh], bh[nt][hh + 1]);
                }
            }
        }
    }

    // ---- epilogue: add bias, store out[a][b][d] ----
    const int tq = lane & 3;    // -> d pair
    const int tg = lane >> 2;   // -> row within 8
    #pragma unroll
    for (int nb = 0; nb < 4; ++nb) {
        const int d = d0 + wn * 32 + nb * 8 + 2 * tq;
        const float2 bv = *(const float2*)(br + d);
        #pragma unroll
        for (int mt = 0; mt < 4; ++mt) {
            const int a0r = (wm * 4 + mt) * 16 + tg;
            float2 o0, o1;
            o0.x = acc[mt][nb][0] + bv.x;
            o0.y = acc[mt][nb][1] + bv.y;
            o1.x = acc[mt][nb][2] + bv.x;
            o1.y = acc[mt][nb][3] + bv.y;
            *(float2*)(out + ((size_t)a0r * 128 + b) * 512 + d)       = o0;
            *(float2*)(out + ((size_t)(a0r + 8) * 128 + b) * 512 + d) = o1;
        }
    }
}

extern "C" void kernel_launch(void* const* d_in, const int* in_sizes, int n_in,
                              void* d_out, int out_size) {
    const float*        x    = (const float*)d_in[0];
    const unsigned int* ridx = (const unsigned int*)d_in[1];
    const float*        w    = (const float*)d_in[2];
    const float*        bias = (const float*)d_in[3];
    float*              out  = (float*)d_out;

    const int Bn = in_sizes[1] > 128 ? 128 : in_sizes[1];
    decode_idx_kernel<<<1, 128>>>(ridx, Bn);

    cudaFuncSetAttribute(linemb_mma, cudaFuncAttributeMaxDynamicSharedMemorySize, SMEM_TOTAL);
    dim3 grid(4, 128);   // (d-tiles, b)
    linemb_mma<<<grid, 256, SMEM_TOTAL>>>(x, w, bias, out);
}

// round 13
// speedup vs baseline: 1.6452x; 1.2521x over previous
#include <cuda_runtime.h>
#include <cuda_fp16.h>
#include <cstdint>

// LinearEmbedded via fp16 mma.sync, warp-specialized producer/consumer.
// out[a,b,d] = sum_c x[a,b,c]*W[r_b,c,d] + bias[r_b,d]; A=B=128, C=D=512.
// R12: 384 thr = 8 consumer warps (ldsm+mma) + 4 producer warps
// (cp.async fp32 3-stage ring -> convert -> fp16 2-stage ring).
// Rendezvous via named barriers (bar.arrive/bar.sync), NO __syncthreads in
// the main loop -> producers issue loads continuously (fix for the measured
// ~2.3TB/s lumpy-issue plateau).
// CTA tile 128(a) x 128(d), K-chunk 32, grid (4,128)=512 CTAs, 1 CTA/SM.

__device__ int g_ridx[128];

__global__ void decode_idx_kernel(const unsigned int* __restrict__ p, int n) {
    __shared__ int not_i64;
    if (threadIdx.x == 0) not_i64 = 0;
    __syncthreads();
    if (threadIdx.x < 64) {
        if (p[2 * threadIdx.x + 1] != 0u) not_i64 = 1;
    }
    __syncthreads();
    int b = (int)threadIdx.x;
    if (b < n) g_ridx[b] = not_i64 ? (int)p[b] : (int)p[2 * b];
}

__device__ __forceinline__ uint32_t smem_u32(const void* p) {
    uint32_t a;
    asm("{ .reg .u64 t; cvta.to.shared.u64 t, %1; cvt.u32.u64 %0, t; }" : "=r"(a) : "l"(p));
    return a;
}
__device__ __forceinline__ uint32_t cvt2(float v0, float v1) {
    __half2 h = __floats2half2_rn(v0, v1);
    return *(uint32_t*)&h;
}
__device__ __forceinline__ void cp16(uint32_t dst, const void* src) {
    asm volatile("cp.async.cg.shared.global [%0], [%1], 16;" :: "r"(dst), "l"(src) : "memory");
}
__device__ __forceinline__ void ldsm4(uint32_t* r, uint32_t addr) {
    asm volatile("ldmatrix.sync.aligned.m8n8.x4.shared.b16 {%0,%1,%2,%3}, [%4];"
        : "=r"(r[0]), "=r"(r[1]), "=r"(r[2]), "=r"(r[3]) : "r"(addr));
}
__device__ __forceinline__ void mma16816(float* d, const uint32_t* a, uint32_t b0, uint32_t b1) {
    asm volatile("mma.sync.aligned.m16n8k16.row.col.f32.f16.f16.f32 "
        "{%0,%1,%2,%3}, {%4,%5,%6,%7}, {%8,%9}, {%0,%1,%2,%3};"
        : "+f"(d[0]), "+f"(d[1]), "+f"(d[2]), "+f"(d[3])
        : "r"(a[0]), "r"(a[1]), "r"(a[2]), "r"(a[3]), "r"(b0), "r"(b1));
}

#define BAR_SYNC(id, cnt)   asm volatile("bar.sync %0, %1;"   :: "r"(id), "r"(cnt) : "memory")
#define BAR_ARRIVE(id, cnt) asm volatile("bar.arrive %0, %1;" :: "r"(id), "r"(cnt) : "memory")
// barrier ids: FULL0=1 FULL1=2 EMPTY0=3 EMPTY1=4 PROD=5

// SMEM map (dynamic):
//  XF: 3 stages x (128 rows x 144B pitch) = 55296   (fp32 x; pad -> LDS.128 conflict-free)
//  WF: 3 stages x (32k x 512B)           = 49152   (fp32 W, [k][d])
//  H : 2 stages x 16KB                    = 32768   (fp16 ldsm lane-order tiles)
#define XF_OFF 0
#define XF_STAGE 18432
#define WF_OFF 55296
#define WF_STAGE 16384
#define H_OFF 104448
#define H_STAGE 16384
#define HA_OFF 0
#define HB_OFF 8192
#define SMEM_TOTAL 137216

__global__ __launch_bounds__(384, 1)
void linemb_mma(const float* __restrict__ x,
                const float* __restrict__ w,
                const float* __restrict__ bias,
                float* __restrict__ out) {
    extern __shared__ __align__(16) char smem[];
    const uint32_t sb = smem_u32(smem);

    const int tid  = (int)threadIdx.x;
    const int wid  = tid >> 5;
    const int lane = tid & 31;
    const int b    = (int)blockIdx.y;
    const int d0   = (int)blockIdx.x * 128;
    const int r    = g_ridx[b];

    const float* __restrict__ xb = x + (size_t)b * 512;          // + a*65536 + c
    const float* __restrict__ wr = w + (size_t)r * 512 * 512;    // + c*512 + d
    const float* __restrict__ br = bias + (size_t)r * 512;

    if (tid >= 256) {
        // ================= PRODUCER (warps 8-11, 128 threads) =================
        const int ptid = tid - 256;

        // fp16-tile store offsets for all 4 octets (row = ptid: x->a, W->d)
        uint32_t aoff[4], boff[4];
        {
            const int n = ptid & 15, t16 = ptid >> 4;
            #pragma unroll
            for (int o = 0; o < 4; ++o) {
                const int k16 = o >> 1, oc = o & 1;
                aoff[o] = (uint32_t)((k16 * 8 + t16) * 512 + ((n & 7) + 8 * ((n >> 3) & 1) + 16 * oc) * 16);
                boff[o] = (uint32_t)((k16 * 8 + t16) * 512 + ((n & 7) + 8 * (oc + 2 * (n >> 3))) * 16);
            }
        }

        // ---- prologue: stage chunks 0..2 ----
        #pragma unroll
        for (int s = 0; s < 3; ++s) {
            const int k0 = s * 32;
            const uint32_t xfs = sb + XF_OFF + (uint32_t)(s * XF_STAGE);
            const uint32_t wfs = sb + WF_OFF + (uint32_t)(s * WF_STAGE);
            #pragma unroll
            for (int j = 0; j < 8; ++j) {            // x: 1024 granules
                const int g = ptid + 128 * j;
                const int row = g >> 3, seg = g & 7;
                cp16(xfs + (uint32_t)(row * 144 + seg * 16),
                     xb + (size_t)row * 65536 + k0 + seg * 4);
            }
            #pragma unroll
            for (int j = 0; j < 8; ++j) {            // W: 1024 granules
                const int g = ptid + 128 * j;
                const int k = g >> 5, seg = g & 31;
                cp16(wfs + (uint32_t)(k * 512 + seg * 16),
                     wr + (size_t)(k0 + k) * 512 + d0 + seg * 4);
            }
            asm volatile("cp.async.commit_group;" ::: "memory");
        }

        for (int ch = 0; ch < 16; ++ch) {
            const uint32_t xfs = sb + XF_OFF + (uint32_t)((ch % 3) * XF_STAGE);
            const uint32_t wfs = sb + WF_OFF + (uint32_t)((ch % 3) * WF_STAGE);
            const uint32_t hs  = sb + H_OFF  + (uint32_t)((ch & 1) * H_STAGE);

            asm volatile("cp.async.wait_group 2;" ::: "memory");
            BAR_SYNC(5, 128);                         // stage ch visible to all producers
            if (ch >= 2) BAR_SYNC(3 + (ch & 1), 384); // fp16 slot free (consumers arrived)

            // convert x row ptid (4 octets)
            #pragma unroll
            for (int o = 0; o < 4; ++o) {
                float4 q0, q1;
                asm volatile("ld.shared.v4.f32 {%0,%1,%2,%3}, [%4];"
                    : "=f"(q0.x), "=f"(q0.y), "=f"(q0.z), "=f"(q0.w)
                    : "r"(xfs + (uint32_t)(ptid * 144 + o * 32)));
                asm volatile("ld.shared.v4.f32 {%0,%1,%2,%3}, [%4];"
                    : "=f"(q1.x), "=f"(q1.y), "=f"(q1.z), "=f"(q1.w)
                    : "r"(xfs + (uint32_t)(ptid * 144 + o * 32 + 16)));
                uint32_t h0 = cvt2(q0.x, q0.y), h1 = cvt2(q0.z, q0.w);
                uint32_t h2 = cvt2(q1.x, q1.y), h3 = cvt2(q1.z, q1.w);
                asm volatile("st.shared.v4.b32 [%0], {%1,%2,%3,%4};"
                    :: "r"(hs + HA_OFF + aoff[o]), "r"(h0), "r"(h1), "r"(h2), "r"(h3) : "memory");
            }
            // convert W column d=ptid (4 octets, 8 strided k each)
            #pragma unroll
            for (int o = 0; o < 4; ++o) {
                float v[8];
                #pragma unroll
                for (int i = 0; i < 8; ++i)
                    asm volatile("ld.shared.f32 %0, [%1];"
                        : "=f"(v[i]) : "r"(wfs + (uint32_t)((o * 8 + i) * 512 + ptid * 4)));
                uint32_t h0 = cvt2(v[0], v[1]), h1 = cvt2(v[2], v[3]);
                uint32_t h2 = cvt2(v[4], v[5]), h3 = cvt2(v[6], v[7]);
                asm volatile("st.shared.v4.b32 [%0], {%1,%2,%3,%4};"
                    :: "r"(hs + HB_OFF + boff[o]), "r"(h0), "r"(h1), "r"(h2), "r"(h3) : "memory");
            }

            asm volatile("membar.cta;" ::: "memory"); // STS visible before FULL
            BAR_ARRIVE(1 + (ch & 1), 384);            // fp16 slot full
            BAR_SYNC(5, 128);                         // all converts done before refill

            if (ch + 3 < 16) {
                const int k0 = (ch + 3) * 32;
                #pragma unroll
                for (int j = 0; j < 8; ++j) {
                    const int g = ptid + 128 * j;
                    const int row = g >> 3, seg = g & 7;
                    cp16(xfs + (uint32_t)(row * 144 + seg * 16),
                         xb + (size_t)row * 65536 + k0 + seg * 4);
                }
                #pragma unroll
                for (int j = 0; j < 8; ++j) {
                    const int g = ptid + 128 * j;
                    const int k = g >> 5, seg = g & 31;
                    cp16(wfs + (uint32_t)(k * 512 + seg * 16),
                         wr + (size_t)(k0 + k) * 512 + d0 + seg * 4);
                }
            }
            asm volatile("cp.async.commit_group;" ::: "memory");
        }
    } else {
        // ================= CONSUMER (warps 0-7, 256 threads) =================
        float acc[4][4][4];
        #pragma unroll
        for (int mt = 0; mt < 4; ++mt)
            #pragma unroll
            for (int nb = 0; nb < 4; ++nb)
                #pragma unroll
                for (int q = 0; q < 4; ++q)
                    acc[mt][nb][q] = 0.0f;

        const int wm = wid & 1;   // 2 m-groups of 64 (a)
        const int wn = wid >> 1;  // 4 n-groups of 32 (d)

        for (int ch = 0; ch < 16; ++ch) {
            const uint32_t hs = sb + H_OFF + (uint32_t)((ch & 1) * H_STAGE);
            BAR_SYNC(1 + (ch & 1), 384);              // wait slot full

            #pragma unroll
            for (int k16 = 0; k16 < 2; ++k16) {
                uint32_t ah[4][4], bh[2][4];
                const uint32_t lof = (uint32_t)lane * 16;
                #pragma unroll
                for (int mt = 0; mt < 4; ++mt)
                    ldsm4(ah[mt], hs + HA_OFF + (uint32_t)((k16 * 8 + wm * 4 + mt) * 512) + lof);
                #pragma unroll
                for (int nt = 0; nt < 2; ++nt)
                    ldsm4(bh[nt], hs + HB_OFF + (uint32_t)((k16 * 8 + wn * 2 + nt) * 512) + lof);
                #pragma unroll
                for (int mt = 0; mt < 4; ++mt) {
                    #pragma unroll
                    for (int nb = 0; nb < 4; ++nb) {
                        const int nt = nb >> 1, hh = (nb & 1) * 2;
                        mma16816(acc[mt][nb], ah[mt], bh[nt][hh], bh[nt][hh + 1]);
                    }
                }
            }
            // mmas consumed every ldsm reg -> reads retired; slot reusable
            BAR_ARRIVE(3 + (ch & 1), 384);
        }

        // ---- epilogue: add bias, store out[a][b][d] ----
        const int tq = lane & 3;
        const int tg = lane >> 2;
        #pragma unroll
        for (int nb = 0; nb < 4; ++nb) {
            const int d = d0 + wn * 32 + nb * 8 + 2 * tq;
            const float2 bv = *(const float2*)(br + d);
            #pragma unroll
            for (int mt = 0; mt < 4; ++mt) {
                const int a0r = (wm * 4 + mt) * 16 + tg;
                float2 o0, o1;
                o0.x = acc[mt][nb][0] + bv.x;
                o0.y = acc[mt][nb][1] + bv.y;
                o1.x = acc[mt][nb][2] + bv.x;
                o1.y = acc[mt][nb][3] + bv.y;
                *(float2*)(out + ((size_t)a0r * 128 + b) * 512 + d)       = o0;
                *(float2*)(out + ((size_t)(a0r + 8) * 128 + b) * 512 + d) = o1;
            }
        }
    }
}

extern "C" void kernel_launch(void* const* d_in, const int* in_sizes, int n_in,
                              void* d_out, int out_size) {
    const float*        x    = (const float*)d_in[0];
    const unsigned int* ridx = (const unsigned int*)d_in[1];
    const float*        w    = (const float*)d_in[2];
    const float*        bias = (const float*)d_in[3];
    float*              out  = (float*)d_out;

    const int Bn = in_sizes[1] > 128 ? 128 : in_sizes[1];
    decode_idx_kernel<<<1, 128>>>(ridx, Bn);

    cudaFuncSetAttribute(linemb_mma, cudaFuncAttributeMaxDynamicSharedMemorySize, SMEM_TOTAL);
    dim3 grid(4, 128);   // (d-tiles, b)
    linemb_mma<<<grid, 384, SMEM_TOTAL>>>(x, w, bias, out);
}

// round 16
// speedup vs baseline: 1.8130x; 1.1020x over previous
#include <cuda_runtime.h>
#include <cuda_fp16.h>
#include <cstdint>

// LinearEmbedded via fp16 mma.sync, warp-specialized producer/consumer.
// out[a,b,d] = sum_c x[a,b,c]*W[r_b,c,d] + bias[r_b,d]; A=B=128, C=D=512.
// R14 (= R13 resubmit after infra failure): 512 thr = 8 consumer warps
// (ldsm+mma) + 8 producer warps (cp.async fp32 4-stage ring -> convert ->
// fp16 2-stage ring). Producer convert work per thread = 2 octets.
// Named-barrier rendezvous, no __syncthreads in main loop.
// CTA tile 128(a) x 128(d), K-chunk 32, grid (4,128)=512 CTAs, 1 CTA/SM.

__device__ int g_ridx[128];

__global__ void decode_idx_kernel(const unsigned int* __restrict__ p, int n) {
    __shared__ int not_i64;
    if (threadIdx.x == 0) not_i64 = 0;
    __syncthreads();
    if (threadIdx.x < 64) {
        if (p[2 * threadIdx.x + 1] != 0u) not_i64 = 1;
    }
    __syncthreads();
    int b = (int)threadIdx.x;
    if (b < n) g_ridx[b] = not_i64 ? (int)p[b] : (int)p[2 * b];
}

__device__ __forceinline__ uint32_t smem_u32(const void* p) {
    uint32_t a;
    asm("{ .reg .u64 t; cvta.to.shared.u64 t, %1; cvt.u32.u64 %0, t; }" : "=r"(a) : "l"(p));
    return a;
}
__device__ __forceinline__ uint32_t cvt2(float v0, float v1) {
    __half2 h = __floats2half2_rn(v0, v1);
    return *(uint32_t*)&h;
}
__device__ __forceinline__ void cp16(uint32_t dst, const void* src) {
    asm volatile("cp.async.cg.shared.global [%0], [%1], 16;" :: "r"(dst), "l"(src) : "memory");
}
__device__ __forceinline__ void ldsm4(uint32_t* r, uint32_t addr) {
    asm volatile("ldmatrix.sync.aligned.m8n8.x4.shared.b16 {%0,%1,%2,%3}, [%4];"
        : "=r"(r[0]), "=r"(r[1]), "=r"(r[2]), "=r"(r[3]) : "r"(addr));
}
__device__ __forceinline__ void mma16816(float* d, const uint32_t* a, uint32_t b0, uint32_t b1) {
    asm volatile("mma.sync.aligned.m16n8k16.row.col.f32.f16.f16.f32 "
        "{%0,%1,%2,%3}, {%4,%5,%6,%7}, {%8,%9}, {%0,%1,%2,%3};"
        : "+f"(d[0]), "+f"(d[1]), "+f"(d[2]), "+f"(d[3])
        : "r"(a[0]), "r"(a[1]), "r"(a[2]), "r"(a[3]), "r"(b0), "r"(b1));
}

#define BAR_SYNC(id, cnt)   asm volatile("bar.sync %0, %1;"   :: "r"(id), "r"(cnt) : "memory")
#define BAR_ARRIVE(id, cnt) asm volatile("bar.arrive %0, %1;" :: "r"(id), "r"(cnt) : "memory")
// barrier ids: FULL0=1 FULL1=2 EMPTY0=3 EMPTY1=4 (count 512), PROD=5 (count 256)

// SMEM map (dynamic):
//  XF: 4 stages x (128 rows x 144B pitch) = 73728  (fp32 x)
//  WF: 4 stages x (32k x 512B)            = 65536  (fp32 W, [k][d])
//  H : 2 stages x 16KB                    = 32768  (fp16 ldsm lane-order tiles)
#define XF_OFF 0
#define XF_STAGE 18432
#define WF_OFF 73728
#define WF_STAGE 16384
#define H_OFF 139264
#define H_STAGE 16384
#define HA_OFF 0
#define HB_OFF 8192
#define SMEM_TOTAL 172032

__global__ __launch_bounds__(512, 1)
void linemb_mma(const float* __restrict__ x,
                const float* __restrict__ w,
                const float* __restrict__ bias,
                float* __restrict__ out) {
    extern __shared__ __align__(16) char smem[];
    const uint32_t sb = smem_u32(smem);

    const int tid  = (int)threadIdx.x;
    const int wid  = tid >> 5;
    const int lane = tid & 31;
    const int b    = (int)blockIdx.y;
    const int d0   = (int)blockIdx.x * 128;
    const int r    = g_ridx[b];

    const float* __restrict__ xb = x + (size_t)b * 512;          // + a*65536 + c
    const float* __restrict__ wr = w + (size_t)r * 512 * 512;    // + c*512 + d
    const float* __restrict__ br = bias + (size_t)r * 512;

    if (tid >= 256) {
        // ================= PRODUCER (warps 8-15, 256 threads) =================
        const int ptid = tid - 256;

        // convert mapping: row = ptid&127 (x->a, W->d), 2 octets o0 = (ptid>>7)*2
        const int c_row = ptid & 127;
        const int c_o0  = (ptid >> 7) * 2;
        uint32_t aoff[2], boff[2];
        {
            const int n = c_row & 15, t16 = c_row >> 4;
            #pragma unroll
            for (int j = 0; j < 2; ++j) {
                const int o = c_o0 + j, k16 = o >> 1, oc = o & 1;
                aoff[j] = (uint32_t)((k16 * 8 + t16) * 512 + ((n & 7) + 8 * ((n >> 3) & 1) + 16 * oc) * 16);
                boff[j] = (uint32_t)((k16 * 8 + t16) * 512 + ((n & 7) + 8 * (oc + 2 * (n >> 3))) * 16);
            }
        }

        // ---- prologue: stage chunks 0..3 (4 x-granules + 4 W-granules each) ----
        #pragma unroll
        for (int s = 0; s < 4; ++s) {
            const int k0 = s * 32;
            const uint32_t xfs = sb + XF_OFF + (uint32_t)(s * XF_STAGE);
            const uint32_t wfs = sb + WF_OFF + (uint32_t)(s * WF_STAGE);
            #pragma unroll
            for (int j = 0; j < 4; ++j) {            // x: 1024 granules / 256 thr
                const int g = ptid + 256 * j;
                const int row = g >> 3, seg = g & 7;
                cp16(xfs + (uint32_t)(row * 144 + seg * 16),
                     xb + (size_t)row * 65536 + k0 + seg * 4);
            }
            #pragma unroll
            for (int j = 0; j < 4; ++j) {            // W: 1024 granules / 256 thr
                const int g = ptid + 256 * j;
                const int k = g >> 5, seg = g & 31;
                cp16(wfs + (uint32_t)(k * 512 + seg * 16),
                     wr + (size_t)(k0 + k) * 512 + d0 + seg * 4);
            }
            asm volatile("cp.async.commit_group;" ::: "memory");
        }

        for (int ch = 0; ch < 16; ++ch) {
            const uint32_t xfs = sb + XF_OFF + (uint32_t)((ch & 3) * XF_STAGE);
            const uint32_t wfs = sb + WF_OFF + (uint32_t)((ch & 3) * WF_STAGE);
            const uint32_t hs  = sb + H_OFF  + (uint32_t)((ch & 1) * H_STAGE);

            asm volatile("cp.async.wait_group 3;" ::: "memory");
            BAR_SYNC(5, 256);                         // stage ch visible to all producers
            if (ch >= 2) BAR_SYNC(3 + (ch & 1), 512); // fp16 slot free

            // convert x row c_row (2 octets)
            #pragma unroll
            for (int j = 0; j < 2; ++j) {
                const int o = c_o0 + j;
                float4 q0, q1;
                asm volatile("ld.shared.v4.f32 {%0,%1,%2,%3}, [%4];"
                    : "=f"(q0.x), "=f"(q0.y), "=f"(q0.z), "=f"(q0.w)
                    : "r"(xfs + (uint32_t)(c_row * 144 + o * 32)));
                asm volatile("ld.shared.v4.f32 {%0,%1,%2,%3}, [%4];"
                    : "=f"(q1.x), "=f"(q1.y), "=f"(q1.z), "=f"(q1.w)
                    : "r"(xfs + (uint32_t)(c_row * 144 + o * 32 + 16)));
                uint32_t h0 = cvt2(q0.x, q0.y), h1 = cvt2(q0.z, q0.w);
                uint32_t h2 = cvt2(q1.x, q1.y), h3 = cvt2(q1.z, q1.w);
                asm volatile("st.shared.v4.b32 [%0], {%1,%2,%3,%4};"
                    :: "r"(hs + HA_OFF + aoff[j]), "r"(h0), "r"(h1), "r"(h2), "r"(h3) : "memory");
            }
            // convert W column d=c_row (2 octets, 8 strided k each)
            #pragma unroll
            for (int j = 0; j < 2; ++j) {
                const int o = c_o0 + j;
                float v[8];
                #pragma unroll
                for (int i = 0; i < 8; ++i)
                    asm volatile("ld.shared.f32 %0, [%1];"
                        : "=f"(v[i]) : "r"(wfs + (uint32_t)((o * 8 + i) * 512 + c_row * 4)));
                uint32_t h0 = cvt2(v[0], v[1]), h1 = cvt2(v[2], v[3]);
                uint32_t h2 = cvt2(v[4], v[5]), h3 = cvt2(v[6], v[7]);
                asm volatile("st.shared.v4.b32 [%0], {%1,%2,%3,%4};"
                    :: "r"(hs + HB_OFF + boff[j]), "r"(h0), "r"(h1), "r"(h2), "r"(h3) : "memory");
            }

            asm volatile("membar.cta;" ::: "memory"); // STS visible before FULL
            BAR_ARRIVE(1 + (ch & 1), 512);            // fp16 slot full
            BAR_SYNC(5, 256);                         // all converts done before refill

            if (ch + 4 < 16) {
                const int k0 = (ch + 4) * 32;
                #pragma unroll
                for (int j = 0; j < 4; ++j) {
                    const int g = ptid + 256 * j;
                    const int row = g >> 3, seg = g & 7;
                    cp16(xfs + (uint32_t)(row * 144 + seg * 16),
                         xb + (size_t)row * 65536 + k0 + seg * 4);
                }
                #pragma unroll
                for (int j = 0; j < 4; ++j) {
                    const int g = ptid + 256 * j;
                    const int k = g >> 5, seg = g & 31;
                    cp16(wfs + (uint32_t)(k * 512 + seg * 16),
                         wr + (size_t)(k0 + k) * 512 + d0 + seg * 4);
                }
            }
            asm volatile("cp.async.commit_group;" ::: "memory");
        }
    } else {
        // ================= CONSUMER (warps 0-7, 256 threads) =================
        float acc[4][4][4];
        #pragma unroll
        for (int mt = 0; mt < 4; ++mt)
            #pragma unroll
            for (int nb = 0; nb < 4; ++nb)
                #pragma unroll
                for (int q = 0; q < 4; ++q)
                    acc[mt][nb][q] = 0.0f;

        const int wm = wid & 1;   // 2 m-groups of 64 (a)
        const int wn = wid >> 1;  // 4 n-groups of 32 (d)

        for (int ch = 0; ch < 16; ++ch) {
            const uint32_t hs = sb + H_OFF + (uint32_t)((ch & 1) * H_STAGE);
            BAR_SYNC(1 + (ch & 1), 512);              // wait slot full

            #pragma unroll
            for (int k16 = 0; k16 < 2; ++k16) {
                uint32_t ah[4][4], bh[2][4];
                const uint32_t lof = (uint32_t)lane * 16;
                #pragma unroll
                for (int mt = 0; mt < 4; ++mt)
                    ldsm4(ah[mt], hs + HA_OFF + (uint32_t)((k16 * 8 + wm * 4 + mt) * 512) + lof);
                #pragma unroll
                for (int nt = 0; nt < 2; ++nt)
                    ldsm4(bh[nt], hs + HB_OFF + (uint32_t)((k16 * 8 + wn * 2 + nt) * 512) + lof);
                #pragma unroll
                for (int mt = 0; mt < 4; ++mt) {
                    #pragma unroll
                    for (int nb = 0; nb < 4; ++nb) {
                        const int nt = nb >> 1, hh = (nb & 1) * 2;
                        mma16816(acc[mt][nb], ah[mt], bh[nt][hh], bh[nt][hh + 1]);
                    }
                }
            }
            BAR_ARRIVE(3 + (ch & 1), 512);            // slot consumed
        }

        // ---- epilogue: add bias, store out[a][b][d] ----
        const int tq = lane & 3;
        const int tg = lane >> 2;
        #pragma unroll
        for (int nb = 0; nb < 4; ++nb) {
            const int d = d0 + wn * 32 + nb * 8 + 2 * tq;
            const float2 bv = *(const float2*)(br + d);
            #pragma unroll
            for (int mt = 0; mt < 4; ++mt) {
                const int a0r = (wm * 4 + mt) * 16 + tg;
                float2 o0, o1;
                o0.x = acc[mt][nb][0] + bv.x;
                o0.y = acc[mt][nb][1] + bv.y;
                o1.x = acc[mt][nb][2] + bv.x;
                o1.y = acc[mt][nb][3] + bv.y;
                *(float2*)(out + ((size_t)a0r * 128 + b) * 512 + d)       = o0;
                *(float2*)(out + ((size_t)(a0r + 8) * 128 + b) * 512 + d) = o1;
            }
        }
    }
}

extern "C" void kernel_launch(void* const* d_in, const int* in_sizes, int n_in,
                              void* d_out, int out_size) {
    const float*        x    = (const float*)d_in[0];
    const unsigned int* ridx = (const unsigned int*)d_in[1];
    const float*        w    = (const float*)d_in[2];
    const float*        bias = (const float*)d_in[3];
    float*              out  = (float*)d_out;

    const int Bn = in_sizes[1] > 128 ? 128 : in_sizes[1];
    decode_idx_kernel<<<1, 128>>>(ridx, Bn);

    cudaFuncSetAttribute(linemb_mma, cudaFuncAttributeMaxDynamicSharedMemorySize, SMEM_TOTAL);
    dim3 grid(4, 128);   // (d-tiles, b)
    linemb_mma<<<grid, 512, SMEM_TOTAL>>>(x, w, bias, out);
}

// round 17
// speedup vs baseline: 1.8700x; 1.0314x over previous
#include <cuda_runtime.h>
#include <cuda_fp16.h>
#include <cstdint>

// LinearEmbedded via fp16 mma.sync, warp-specialized producer/consumer.
// out[a,b,d] = sum_c x[a,b,c]*W[r_b,c,d] + bias[r_b,d]; A=B=128, C=D=512.
// R16: early-refill producer loop (cp.async refill issued BEFORE converts ->
// no load-issue dead zone) + fp16 ring deepened to 3 stages.
// 512 thr = 8 consumer warps (ldsm+mma) + 8 producer warps.
// CTA tile 128(a) x 128(d), K-chunk 32, grid (4,128)=512 CTAs, 1 CTA/SM.

__device__ int g_ridx[128];

__global__ void decode_idx_kernel(const unsigned int* __restrict__ p, int n) {
    __shared__ int not_i64;
    if (threadIdx.x == 0) not_i64 = 0;
    __syncthreads();
    if (threadIdx.x < 64) {
        if (p[2 * threadIdx.x + 1] != 0u) not_i64 = 1;
    }
    __syncthreads();
    int b = (int)threadIdx.x;
    if (b < n) g_ridx[b] = not_i64 ? (int)p[b] : (int)p[2 * b];
}

__device__ __forceinline__ uint32_t smem_u32(const void* p) {
    uint32_t a;
    asm("{ .reg .u64 t; cvta.to.shared.u64 t, %1; cvt.u32.u64 %0, t; }" : "=r"(a) : "l"(p));
    return a;
}
__device__ __forceinline__ uint32_t cvt2(float v0, float v1) {
    __half2 h = __floats2half2_rn(v0, v1);
    return *(uint32_t*)&h;
}
__device__ __forceinline__ void cp16(uint32_t dst, const void* src) {
    asm volatile("cp.async.cg.shared.global [%0], [%1], 16;" :: "r"(dst), "l"(src) : "memory");
}
__device__ __forceinline__ void ldsm4(uint32_t* r, uint32_t addr) {
    asm volatile("ldmatrix.sync.aligned.m8n8.x4.shared.b16 {%0,%1,%2,%3}, [%4];"
        : "=r"(r[0]), "=r"(r[1]), "=r"(r[2]), "=r"(r[3]) : "r"(addr));
}
__device__ __forceinline__ void mma16816(float* d, const uint32_t* a, uint32_t b0, uint32_t b1) {
    asm volatile("mma.sync.aligned.m16n8k16.row.col.f32.f16.f16.f32 "
        "{%0,%1,%2,%3}, {%4,%5,%6,%7}, {%8,%9}, {%0,%1,%2,%3};"
        : "+f"(d[0]), "+f"(d[1]), "+f"(d[2]), "+f"(d[3])
        : "r"(a[0]), "r"(a[1]), "r"(a[2]), "r"(a[3]), "r"(b0), "r"(b1));
}

#define BAR_SYNC(id, cnt)   asm volatile("bar.sync %0, %1;"   :: "r"(id), "r"(cnt) : "memory")
#define BAR_ARRIVE(id, cnt) asm volatile("bar.arrive %0, %1;" :: "r"(id), "r"(cnt) : "memory")
// ids: FULL = 1 + ch%3, EMPTY = 4 + ch%3 (count 512); PROD = 7 (count 256)

// SMEM map (dynamic):
//  XF: 4 slots x (128 rows x 144B pitch) = 73728  (fp32 x)
//  WF: 4 slots x (32k x 512B)            = 65536  (fp32 W, [k][d])
//  H : 3 stages x 16KB                   = 49152  (fp16 ldsm lane-order tiles)
#define XF_OFF 0
#define XF_STAGE 18432
#define WF_OFF 73728
#define WF_STAGE 16384
#define H_OFF 139264
#define H_STAGE 16384
#define HA_OFF 0
#define HB_OFF 8192
#define SMEM_TOTAL 188416

__global__ __launch_bounds__(512, 1)
void linemb_mma(const float* __restrict__ x,
                const float* __restrict__ w,
                const float* __restrict__ bias,
                float* __restrict__ out) {
    extern __shared__ __align__(16) char smem[];
    const uint32_t sb = smem_u32(smem);

    const int tid  = (int)threadIdx.x;
    const int wid  = tid >> 5;
    const int lane = tid & 31;
    const int b    = (int)blockIdx.y;
    const int d0   = (int)blockIdx.x * 128;
    const int r    = g_ridx[b];

    const float* __restrict__ xb = x + (size_t)b * 512;          // + a*65536 + c
    const float* __restrict__ wr = w + (size_t)r * 512 * 512;    // + c*512 + d
    const float* __restrict__ br = bias + (size_t)r * 512;

    if (tid >= 256) {
        // ================= PRODUCER (warps 8-15, 256 threads) =================
        const int ptid = tid - 256;

        const int c_row = ptid & 127;
        const int c_o0  = (ptid >> 7) * 2;
        uint32_t aoff[2], boff[2];
        {
            const int n = c_row & 15, t16 = c_row >> 4;
            #pragma unroll
            for (int j = 0; j < 2; ++j) {
                const int o = c_o0 + j, k16 = o >> 1, oc = o & 1;
                aoff[j] = (uint32_t)((k16 * 8 + t16) * 512 + ((n & 7) + 8 * ((n >> 3) & 1) + 16 * oc) * 16);
                boff[j] = (uint32_t)((k16 * 8 + t16) * 512 + ((n & 7) + 8 * (oc + 2 * (n >> 3))) * 16);
            }
        }

        // ---- prologue: stage chunks 0..2 into fp32 slots 0..2 ----
        #pragma unroll
        for (int s = 0; s < 3; ++s) {
            const int k0 = s * 32;
            const uint32_t xfs = sb + XF_OFF + (uint32_t)(s * XF_STAGE);
            const uint32_t wfs = sb + WF_OFF + (uint32_t)(s * WF_STAGE);
            #pragma unroll
            for (int j = 0; j < 4; ++j) {
                const int g = ptid + 256 * j;
                const int row = g >> 3, seg = g & 7;
                cp16(xfs + (uint32_t)(row * 144 + seg * 16),
                     xb + (size_t)row * 65536 + k0 + seg * 4);
            }
            #pragma unroll
            for (int j = 0; j < 4; ++j) {
                const int g = ptid + 256 * j;
                const int k = g >> 5, seg = g & 31;
                cp16(wfs + (uint32_t)(k * 512 + seg * 16),
                     wr + (size_t)(k0 + k) * 512 + d0 + seg * 4);
            }
            asm volatile("cp.async.commit_group;" ::: "memory");
        }

        for (int ch = 0; ch < 16; ++ch) {
            const int h3 = ch % 3;
            const uint32_t xfs = sb + XF_OFF + (uint32_t)((ch & 3) * XF_STAGE);
            const uint32_t wfs = sb + WF_OFF + (uint32_t)((ch & 3) * WF_STAGE);
            const uint32_t hs  = sb + H_OFF  + (uint32_t)(h3 * H_STAGE);

            // 1) oldest pending group (chunk ch) done; <=2 younger pending
            asm volatile("cp.async.wait_group 2;" ::: "memory");
            // 2) all producers past iter ch-1 converts; stage ch visible
            BAR_SYNC(7, 256);

            // 3) EARLY REFILL: chunk ch+3 -> slot (ch+3)&3 (= slot converted
            //    at iter ch-1; BAR_SYNC(7) above proves those reads retired)
            if (ch + 3 < 16) {
                const int k0 = (ch + 3) * 32;
                const uint32_t xfn = sb + XF_OFF + (uint32_t)(((ch + 3) & 3) * XF_STAGE);
                const uint32_t wfn = sb + WF_OFF + (uint32_t)(((ch + 3) & 3) * WF_STAGE);
                #pragma unroll
                for (int j = 0; j < 4; ++j) {
                    const int g = ptid + 256 * j;
                    const int row = g >> 3, seg = g & 7;
                    cp16(xfn + (uint32_t)(row * 144 + seg * 16),
                         xb + (size_t)row * 65536 + k0 + seg * 4);
                }
                #pragma unroll
                for (int j = 0; j < 4; ++j) {
                    const int g = ptid + 256 * j;
                    const int k = g >> 5, seg = g & 31;
                    cp16(wfn + (uint32_t)(k * 512 + seg * 16),
                         wr + (size_t)(k0 + k) * 512 + d0 + seg * 4);
                }
            }
            asm volatile("cp.async.commit_group;" ::: "memory");

            // 4) fp16 slot free (consumer of chunk ch-3 arrived)
            if (ch >= 3) BAR_SYNC(4 + h3, 512);

            // 5) convert x row c_row (2 octets)
            #pragma unroll
            for (int j = 0; j < 2; ++j) {
                const int o = c_o0 + j;
                float4 q0, q1;
                asm volatile("ld.shared.v4.f32 {%0,%1,%2,%3}, [%4];"
                    : "=f"(q0.x), "=f"(q0.y), "=f"(q0.z), "=f"(q0.w)
                    : "r"(xfs + (uint32_t)(c_row * 144 + o * 32)));
                asm volatile("ld.shared.v4.f32 {%0,%1,%2,%3}, [%4];"
                    : "=f"(q1.x), "=f"(q1.y), "=f"(q1.z), "=f"(q1.w)
                    : "r"(xfs + (uint32_t)(c_row * 144 + o * 32 + 16)));
                uint32_t h0 = cvt2(q0.x, q0.y), h1 = cvt2(q0.z, q0.w);
                uint32_t h2 = cvt2(q1.x, q1.y), h3r = cvt2(q1.z, q1.w);
                asm volatile("st.shared.v4.b32 [%0], {%1,%2,%3,%4};"
                    :: "r"(hs + HA_OFF + aoff[j]), "r"(h0), "r"(h1), "r"(h2), "r"(h3r) : "memory");
            }
            //    convert W column d=c_row (2 octets, 8 strided k each)
            #pragma unroll
            for (int j = 0; j < 2; ++j) {
                const int o = c_o0 + j;
                float v[8];
                #pragma unroll
                for (int i = 0; i < 8; ++i)
                    asm volatile("ld.shared.f32 %0, [%1];"
                        : "=f"(v[i]) : "r"(wfs + (uint32_t)((o * 8 + i) * 512 + c_row * 4)));
                uint32_t h0 = cvt2(v[0], v[1]), h1 = cvt2(v[2], v[3]);
                uint32_t h2 = cvt2(v[4], v[5]), h3r = cvt2(v[6], v[7]);
                asm volatile("st.shared.v4.b32 [%0], {%1,%2,%3,%4};"
                    :: "r"(hs + HB_OFF + boff[j]), "r"(h0), "r"(h1), "r"(h2), "r"(h3r) : "memory");
            }

            asm volatile("membar.cta;" ::: "memory"); // STS visible before FULL
            BAR_ARRIVE(1 + h3, 512);                  // fp16 slot full
        }
    } else {
        // ================= CONSUMER (warps 0-7, 256 threads) =================
        float acc[4][4][4];
        #pragma unroll
        for (int mt = 0; mt < 4; ++mt)
            #pragma unroll
            for (int nb = 0; nb < 4; ++nb)
                #pragma unroll
                for (int q = 0; q < 4; ++q)
                    acc[mt][nb][q] = 0.0f;

        const int wm = wid & 1;   // 2 m-groups of 64 (a)
        const int wn = wid >> 1;  // 4 n-groups of 32 (d)

        for (int ch = 0; ch < 16; ++ch) {
            const int h3 = ch % 3;
            const uint32_t hs = sb + H_OFF + (uint32_t)(h3 * H_STAGE);
            BAR_SYNC(1 + h3, 512);                    // wait slot full

            #pragma unroll
            for (int k16 = 0; k16 < 2; ++k16) {
                uint32_t ah[4][4], bh[2][4];
                const uint32_t lof = (uint32_t)lane * 16;
                #pragma unroll
                for (int mt = 0; mt < 4; ++mt)
                    ldsm4(ah[mt], hs + HA_OFF + (uint32_t)((k16 * 8 + wm * 4 + mt) * 512) + lof);
                #pragma unroll
                for (int nt = 0; nt < 2; ++nt)
                    ldsm4(bh[nt], hs + HB_OFF + (uint32_t)((k16 * 8 + wn * 2 + nt) * 512) + lof);
                #pragma unroll
                for (int mt = 0; mt < 4; ++mt) {
                    #pragma unroll
                    for (int nb = 0; nb < 4; ++nb) {
                        const int nt = nb >> 1, hh = (nb & 1) * 2;
                        mma16816(acc[mt][nb], ah[mt], bh[nt][hh], bh[nt][hh + 1]);
                    }
                }
            }
            BAR_ARRIVE(4 + h3, 512);                  // slot consumed
        }

        // ---- epilogue: add bias, store out[a][b][d] ----
        const int tq = lane & 3;
        const int tg = lane >> 2;
        #pragma unroll
        for (int nb = 0; nb < 4; ++nb) {
            const int d = d0 + wn * 32 + nb * 8 + 2 * tq;
            const float2 bv = *(const float2*)(br + d);
            #pragma unroll
            for (int mt = 0; mt < 4; ++mt) {
                const int a0r = (wm * 4 + mt) * 16 + tg;
                float2 o0, o1;
                o0.x = acc[mt][nb][0] + bv.x;
                o0.y = acc[mt][nb][1] + bv.y;
                o1.x = acc[mt][nb][2] + bv.x;
                o1.y = acc[mt][nb][3] + bv.y;
                *(float2*)(out + ((size_t)a0r * 128 + b) * 512 + d)       = o0;
                *(float2*)(out + ((size_t)(a0r + 8) * 128 + b) * 512 + d) = o1;
            }
        }
    }
}

extern "C" void kernel_launch(void* const* d_in, const int* in_sizes, int n_in,
                              void* d_out, int out_size) {
    const float*        x    = (const float*)d_in[0];
    const unsigned int* ridx = (const unsigned int*)d_in[1];
    const float*        w    = (const float*)d_in[2];
    const float*        bias = (const float*)d_in[3];
    float*              out  = (float*)d_out;

    const int Bn = in_sizes[1] > 128 ? 128 : in_sizes[1];
    decode_idx_kernel<<<1, 128>>>(ridx, Bn);

    cudaFuncSetAttribute(linemb_mma, cudaFuncAttributeMaxDynamicSharedMemorySize, SMEM_TOTAL);
    dim3 grid(4, 128);   // (d-tiles, b)
    linemb_mma<<<grid, 512, SMEM_TOTAL>>>(x, w, bias, out);
}